// round 5
// baseline (speedup 1.0000x reference)
#include <cuda_runtime.h>
#include <cuda_bf16.h>
#include <cstdint>
#include <cstddef>

#define NNODES 262144
#define NB 64
#define ND 128
#define NG 128
#define NH 128
#define NM 24
#define MAXC 4096
#define NEGV -1.0e9f
#define TILE_M 128
#define NTILES (NNODES / TILE_M)   // 2048

// ---------------- scratch (__device__ globals; no allocs allowed) ----------------
__device__ int d_excl[NNODES];
__device__ int d_gstart[NB];
__device__ int d_blocksum[256];
__device__ int d_blockoff[256];
__device__ int d_mcode[2];         // [0]=cube_mask dtype, [1]=move_mask dtype; 0=u8,1=i32,2=f32

// ---------------- helpers ----------------
__device__ __forceinline__ uint32_t smem_u32(const void* p) {
    uint32_t a;
    asm("{ .reg .u64 t; cvta.to.shared.u64 t, %1; cvt.u32.u64 %0, t; }" : "=r"(a) : "l"(p));
    return a;
}
__device__ __forceinline__ uint32_t packbf(float lo, float hi) {
    uint32_t r;
    asm("cvt.rn.satfinite.bf16x2.f32 %0, %1, %2;" : "=r"(r) : "f"(hi), "f"(lo));
    return r;
}
__device__ __forceinline__ void ldsm4(uint32_t& r0, uint32_t& r1, uint32_t& r2, uint32_t& r3, uint32_t addr) {
    asm volatile("ldmatrix.sync.aligned.m8n8.x4.shared.b16 {%0,%1,%2,%3}, [%4];"
                 : "=r"(r0), "=r"(r1), "=r"(r2), "=r"(r3) : "r"(addr));
}
__device__ __forceinline__ void mma16816(float* c, uint32_t a0, uint32_t a1, uint32_t a2, uint32_t a3,
                                         uint32_t b0, uint32_t b1) {
    asm volatile("mma.sync.aligned.m16n8k16.row.col.f32.bf16.bf16.f32 "
                 "{%0,%1,%2,%3}, {%4,%5,%6,%7}, {%8,%9}, {%0,%1,%2,%3};"
                 : "+f"(c[0]), "+f"(c[1]), "+f"(c[2]), "+f"(c[3])
                 : "r"(a0), "r"(a1), "r"(a2), "r"(a3), "r"(b0), "r"(b1));
}

// generic mask accessors (dtype-code driven)
__device__ __forceinline__ int mask1(const void* p, int i, int code) {
    if (code == 0) return ((const unsigned char*)p)[i] != 0;
    if (code == 1) return ((const int*)p)[i] != 0;
    return ((const float*)p)[i] != 0.0f;
}
__device__ __forceinline__ int4 mask4(const void* p, int i4, int code) {
    // i4 = index of a 4-element aligned group
    if (code == 0) {
        uchar4 m = ((const uchar4*)p)[i4];
        return make_int4(m.x != 0, m.y != 0, m.z != 0, m.w != 0);
    }
    if (code == 1) {
        int4 m = ((const int4*)p)[i4];
        return make_int4(m.x != 0, m.y != 0, m.z != 0, m.w != 0);
    }
    float4 m = ((const float4*)p)[i4];
    return make_int4(m.x != 0.0f, m.y != 0.0f, m.z != 0.0f, m.w != 0.0f);
}

// SW128 swizzle + blocked-atom (8 rows x 64 bf16 per atom) byte offsets
__device__ __forceinline__ uint32_t swz(uint32_t o) { return o ^ ((o >> 3) & 0x70); }
// 128-row tiles (A 128x256, W1 128x256, H 128x128): atom stride 16
__device__ __forceinline__ uint32_t abA(int row, int col) {
    uint32_t o = (uint32_t)((row >> 3) + (col >> 6) * 16) * 1024u
               + (uint32_t)(row & 7) * 128u + (uint32_t)(col & 63) * 2u;
    return swz(o);
}
// 32-row tile (W2 padded 32x128): atom stride 4
__device__ __forceinline__ uint32_t abW2(int row, int col) {
    uint32_t o = (uint32_t)((row >> 3) + (col >> 6) * 4) * 1024u
               + (uint32_t)(row & 7) * 128u + (uint32_t)(col & 63) * 2u;
    return swz(o);
}

// ---------------- SMEM layout (bytes) ----------------
#define SM_BATCH   0               // 128*4 = 512
#define SM_B1      512             // 128*4 = 512
#define SM_B2      1024            // 32*4  = 128
#define SM_SC      1152            // 128*33*4 = 16896 (stride-33 f32)
#define SM_A       18432           // 128x256 bf16 = 65536 (1024-aligned)
#define SM_W1      83968           // 128x256 bf16 = 65536
#define SM_H       149504          // 128x128 bf16 = 32768
#define SM_W2      182272          // 32x128 bf16  = 8192
#define SM_GLB     190464          // 64x128 bf16  = 16384
#define SMEM_TOTAL 206848

// ---------------- dtype detection ----------------
__global__ void detect_masks(const uint32_t* __restrict__ cm, const uint32_t* __restrict__ mm) {
    if (threadIdx.x != 0 || blockIdx.x != 0) return;
    #pragma unroll 1
    for (int which = 0; which < 2; which++) {
        const uint32_t* p = which ? mm : cm;
        int isf32 = 0, isu8 = 0;
        #pragma unroll 1
        for (int i = 0; i < 256; i++) {
            uint32_t v = p[i];
            if (v == 0x3F800000u) { isf32 = 1; break; }
            if (v > 1u) isu8 = 1;
        }
        d_mcode[which] = isf32 ? 2 : (isu8 ? 0 : 1);
    }
}

// ---------------- small kernels ----------------
__global__ void fill_neg_kernel(float4* out, int n4) {
    float4 v = make_float4(NEGV, NEGV, NEGV, NEGV);
    for (int i = blockIdx.x * blockDim.x + threadIdx.x; i < n4; i += gridDim.x * blockDim.x)
        out[i] = v;
}

__global__ void scan_partial(const void* __restrict__ mask) {
    int b = blockIdx.x, t = threadIdx.x;
    int code = d_mcode[0];
    int4 m = mask4(mask, b * 256 + t, code);
    int s = m.x + m.y + m.z + m.w;
    for (int o = 16; o; o >>= 1) s += __shfl_down_sync(0xFFFFFFFFu, s, o);
    __shared__ int ws[8];
    if ((t & 31) == 0) ws[t >> 5] = s;
    __syncthreads();
    if (t == 0) {
        int tot = 0;
        #pragma unroll
        for (int i = 0; i < 8; i++) tot += ws[i];
        d_blocksum[b] = tot;
    }
}

__global__ void scan_offsets() {
    int t = threadIdx.x;
    __shared__ int sh[256];
    int own = d_blocksum[t];
    sh[t] = own;
    __syncthreads();
    for (int o = 1; o < 256; o <<= 1) {
        int v = (t >= o) ? sh[t - o] : 0;
        __syncthreads();
        sh[t] += v;
        __syncthreads();
    }
    d_blockoff[t] = sh[t] - own;
}

__global__ void scan_final(const void* __restrict__ mask, const int* __restrict__ batch) {
    int b = blockIdx.x, t = threadIdx.x;
    int n0 = b * 1024 + t * 4;
    int code = d_mcode[0];
    int4 m = mask4(mask, n0 >> 2, code);
    int c0 = m.x, c1 = m.y, c2 = m.z, c3 = m.w;
    int s = c0 + c1 + c2 + c3;
    int lane = t & 31, w = t >> 5;
    int incl = s;
    for (int o = 1; o < 32; o <<= 1) {
        int v = __shfl_up_sync(0xFFFFFFFFu, incl, o);
        if (lane >= o) incl += v;
    }
    __shared__ int wtot[8];
    if (lane == 31) wtot[w] = incl;
    __syncthreads();
    int wbase = 0;
    for (int i = 0; i < w; i++) wbase += wtot[i];
    int e0 = d_blockoff[b] + wbase + incl - s;
    int e1 = e0 + c0, e2 = e1 + c1, e3 = e2 + c2;
    d_excl[n0 + 0] = e0; d_excl[n0 + 1] = e1;
    d_excl[n0 + 2] = e2; d_excl[n0 + 3] = e3;
    int bp = (n0 == 0) ? -1 : batch[n0 - 1];
    int b0 = batch[n0 + 0], b1v = batch[n0 + 1], b2v = batch[n0 + 2], b3v = batch[n0 + 3];
    if (b0 != bp)   d_gstart[b0]  = e0;
    if (b1v != b0)  d_gstart[b1v] = e1;
    if (b2v != b1v) d_gstart[b2v] = e2;
    if (b3v != b2v) d_gstart[b3v] = e3;
}

// ---------------- main fused GEMM kernel (persistent, mma.sync bf16) ----------------
__global__ void __launch_bounds__(256, 1)
cube_gemm_kernel(const float* __restrict__ nf, const float* __restrict__ gf,
                 const float* __restrict__ W1, const float* __restrict__ b1,
                 const float* __restrict__ W2, const float* __restrict__ b2,
                 const void* __restrict__ cmask, const int* __restrict__ batch,
                 const void* __restrict__ mmask, float* __restrict__ out)
{
    extern __shared__ char smem[];
    uint32_t sb = smem_u32(smem);
    int tid = threadIdx.x, wid = tid >> 5, lid = tid & 31;
    const int ccode = d_mcode[0];
    const int mcode = d_mcode[1];

    // ---- one-time staging: W1, W2 (zero-padded to 32 rows), globals bf16, biases ----
    for (int e2 = tid; e2 < 128 * 128; e2 += 256) {            // W1: 128x256 -> bf16x2
        int row = e2 >> 7, col = (e2 & 127) * 2;
        float2 v = *(const float2*)(W1 + row * 256 + col);
        *(uint32_t*)(smem + SM_W1 + abA(row, col)) = packbf(v.x, v.y);
    }
    for (int i = tid; i < 8192 / 4; i += 256)                  // zero W2 pad tile
        ((uint32_t*)(smem + SM_W2))[i] = 0;
    __syncthreads();
    for (int e2 = tid; e2 < 24 * 64; e2 += 256) {              // W2 rows 0..23
        int row = e2 >> 6, col = (e2 & 63) * 2;
        float2 v = *(const float2*)(W2 + row * 128 + col);
        *(uint32_t*)(smem + SM_W2 + abW2(row, col)) = packbf(v.x, v.y);
    }
    for (int e2 = tid; e2 < 64 * 64; e2 += 256) {              // globals -> bf16 [64][128]
        int row = e2 >> 6, col = (e2 & 63) * 2;
        float2 v = *(const float2*)(gf + row * 128 + col);
        *(uint32_t*)(smem + SM_GLB + (row * 128 + col) * 2) = packbf(v.x, v.y);
    }
    if (tid < 128) ((float*)(smem + SM_B1))[tid] = b1[tid];
    if (tid < 32)  ((float*)(smem + SM_B2))[tid] = (tid < NM) ? b2[tid] : 0.0f;
    __syncthreads();

    const float* b1s = (const float*)(smem + SM_B1);
    const float* b2s = (const float*)(smem + SM_B2);
    int* sbatch = (int*)(smem + SM_BATCH);
    float* sc = (float*)(smem + SM_SC);

    const int m0 = wid * 16;           // this warp's row strip
    const int mrow = lid >> 2;         // t/4
    const int kcol2 = (lid & 3) * 2;   // 2*(t%4)

    // ldmatrix lane row/col (within a 16x16 A tile)
    const int lm_row = lid & 15;
    const int lm_kof = (lid >> 4) << 3;

    for (int tile = blockIdx.x; tile < NTILES; tile += gridDim.x) {
        int nbase = tile * TILE_M;
        if (tid < 128) sbatch[tid] = batch[nbase + tid];
        __syncthreads();

        // ---- stage A tile: node part (cols 0..127) ----
        #pragma unroll
        for (int it = 0; it < 16; it++) {
            int i4 = tid + it * 256;
            int row = i4 >> 5, col = (i4 & 31) * 4;
            float4 v = *(const float4*)(nf + (size_t)(nbase + row) * ND + col);
            uint2 pp = make_uint2(packbf(v.x, v.y), packbf(v.z, v.w));
            *(uint2*)(smem + SM_A + abA(row, col)) = pp;
        }
        // ---- A global part: gather staged bf16 (cols 128..255) ----
        #pragma unroll
        for (int it = 0; it < 16; it++) {
            int i4 = tid + it * 256;
            int row = i4 >> 5, col = (i4 & 31) * 4;
            int bg = sbatch[row];
            uint2 pp = *(const uint2*)(smem + SM_GLB + (bg * 128 + col) * 2);
            *(uint2*)(smem + SM_A + abA(row, 128 + col)) = pp;
        }
        __syncthreads();

        // ================= GEMM1: H[128,128] = A[128,256] @ W1^T =================
        {
            float acc[16][4];
            #pragma unroll
            for (int nb = 0; nb < 16; nb++)
                acc[nb][0] = acc[nb][1] = acc[nb][2] = acc[nb][3] = 0.0f;
            for (int kk = 0; kk < 16; kk++) {
                int k0 = kk * 16;
                uint32_t a0, a1, a2, a3;
                ldsm4(a0, a1, a2, a3, sb + SM_A + abA(m0 + lm_row, k0 + lm_kof));
                #pragma unroll
                for (int nbp = 0; nbp < 8; nbp++) {
                    int n0 = nbp * 16;
                    int brow = n0 + (lid & 7) + ((lid >> 4) << 3);
                    int bcol = k0 + (lid & 8);
                    uint32_t b0, b1r, b2r, b3;
                    ldsm4(b0, b1r, b2r, b3, sb + SM_W1 + abA(brow, bcol));
                    mma16816(acc[2 * nbp],     a0, a1, a2, a3, b0, b1r);
                    mma16816(acc[2 * nbp + 1], a0, a1, a2, a3, b2r, b3);
                }
            }
            // epilogue: relu(acc + b1) -> bf16 -> SMEM H (swizzled)
            #pragma unroll
            for (int nb = 0; nb < 16; nb++) {
                int col = nb * 8 + kcol2;
                float f0 = fmaxf(acc[nb][0] + b1s[col],     0.0f);
                float f1 = fmaxf(acc[nb][1] + b1s[col + 1], 0.0f);
                float f2 = fmaxf(acc[nb][2] + b1s[col],     0.0f);
                float f3 = fmaxf(acc[nb][3] + b1s[col + 1], 0.0f);
                *(uint32_t*)(smem + SM_H + abA(m0 + mrow,     col)) = packbf(f0, f1);
                *(uint32_t*)(smem + SM_H + abA(m0 + mrow + 8, col)) = packbf(f2, f3);
            }
        }
        __syncthreads();

        // ================= GEMM2: S[128,32] = H[128,128] @ W2pad^T =================
        {
            float acc[4][4];
            #pragma unroll
            for (int nb = 0; nb < 4; nb++)
                acc[nb][0] = acc[nb][1] = acc[nb][2] = acc[nb][3] = 0.0f;
            #pragma unroll
            for (int kk = 0; kk < 8; kk++) {
                int k0 = kk * 16;
                uint32_t a0, a1, a2, a3;
                ldsm4(a0, a1, a2, a3, sb + SM_H + abA(m0 + lm_row, k0 + lm_kof));
                #pragma unroll
                for (int nbp = 0; nbp < 2; nbp++) {
                    int n0 = nbp * 16;
                    int brow = n0 + (lid & 7) + ((lid >> 4) << 3);
                    int bcol = k0 + (lid & 8);
                    uint32_t b0, b1r, b2r, b3;
                    ldsm4(b0, b1r, b2r, b3, sb + SM_W2 + abW2(brow, bcol));
                    mma16816(acc[2 * nbp],     a0, a1, a2, a3, b0, b1r);
                    mma16816(acc[2 * nbp + 1], a0, a1, a2, a3, b2r, b3);
                }
            }
            // stage scores to SMEM (f32, stride 33)
            #pragma unroll
            for (int nb = 0; nb < 4; nb++) {
                int col = nb * 8 + kcol2;
                sc[(m0 + mrow) * 33 + col]          = acc[nb][0];
                sc[(m0 + mrow) * 33 + col + 1]      = acc[nb][1];
                sc[(m0 + mrow + 8) * 33 + col]      = acc[nb][2];
                sc[(m0 + mrow + 8) * 33 + col + 1]  = acc[nb][3];
            }
        }
        __syncthreads();

        // ---- scatter epilogue: 128 threads, one node-row each ----
        if (tid < 128) {
            int node = nbase + tid;
            if (mask1(cmask, node, ccode)) {
                int bg = sbatch[tid];
                int r = d_excl[node] - d_gstart[bg];
                if (r < MAXC) {
                    size_t base = ((size_t)bg * MAXC + (size_t)r) * NM;
                    const float* srow = sc + tid * 33;
                    #pragma unroll
                    for (int m = 0; m < NM; m++) {
                        if (mask1(mmask, (int)(base + m), mcode))
                            out[base + m] = srow[m] + b2s[m];
                    }
                }
            }
        }
        __syncthreads();
    }
}

// ---------------- launch ----------------
extern "C" void kernel_launch(void* const* d_in, const int* in_sizes, int n_in,
                              void* d_out, int out_size) {
    const float* nf    = (const float*)d_in[0];
    const float* gf    = (const float*)d_in[1];
    const float* W1    = (const float*)d_in[2];
    const float* b1    = (const float*)d_in[3];
    const float* W2    = (const float*)d_in[4];
    const float* b2    = (const float*)d_in[5];
    const void*  cm    = d_in[6];
    const int*   batch = (const int*)d_in[7];
    const void*  mm    = d_in[8];
    float*       out   = (float*)d_out;

    detect_masks<<<1, 32>>>((const uint32_t*)cm, (const uint32_t*)mm);
    fill_neg_kernel<<<2048, 256>>>((float4*)out, out_size / 4);
    scan_partial<<<256, 256>>>(cm);
    scan_offsets<<<1, 256>>>();
    scan_final<<<256, 256>>>(cm, batch);

    int sm = 0;
    cudaDeviceGetAttribute(&sm, cudaDevAttrMultiProcessorCount, 0);
    if (sm <= 0) sm = 148;
    cudaFuncSetAttribute(cube_gemm_kernel, cudaFuncAttributeMaxDynamicSharedMemorySize, SMEM_TOTAL);
    cube_gemm_kernel<<<sm, 256, SMEM_TOTAL>>>(nf, gf, W1, b1, W2, b2, cm, batch, mm, out);
}

// round 6
// speedup vs baseline: 1.6842x; 1.6842x over previous
#include <cuda_runtime.h>
#include <cuda_bf16.h>
#include <cstdint>
#include <cstddef>

#define NNODES 262144
#define NB 64
#define ND 128
#define NH 128
#define NM 24
#define MAXC 4096
#define NEGV -1.0e9f
#define TILE_M 128
#define NTILES (NNODES / TILE_M)   // 2048
#define OUT_ELEMS (NB * MAXC * NM)

// ---------------- scratch ----------------
__device__ int d_excl[NNODES];
__device__ int d_gstart[NB];
__device__ int d_blocksum[256];
__device__ int d_blockoff[256];
__device__ int d_mcode[2];
__device__ unsigned d_barcnt = 0;
__device__ volatile unsigned d_barsense = 0;

// ---------------- helpers ----------------
__device__ __forceinline__ uint32_t smem_u32(const void* p) {
    uint32_t a;
    asm("{ .reg .u64 t; cvta.to.shared.u64 t, %1; cvt.u32.u64 %0, t; }" : "=r"(a) : "l"(p));
    return a;
}
__device__ __forceinline__ uint32_t packbf(float lo, float hi) {
    uint32_t r;
    asm("cvt.rn.satfinite.bf16x2.f32 %0, %1, %2;" : "=r"(r) : "f"(hi), "f"(lo));
    return r;
}
__device__ __forceinline__ void ldsm4(uint32_t& r0, uint32_t& r1, uint32_t& r2, uint32_t& r3, uint32_t addr) {
    asm volatile("ldmatrix.sync.aligned.m8n8.x4.shared.b16 {%0,%1,%2,%3}, [%4];"
                 : "=r"(r0), "=r"(r1), "=r"(r2), "=r"(r3) : "r"(addr));
}
__device__ __forceinline__ void mma16816(float* c, uint32_t a0, uint32_t a1, uint32_t a2, uint32_t a3,
                                         uint32_t b0, uint32_t b1) {
    asm volatile("mma.sync.aligned.m16n8k16.row.col.f32.bf16.bf16.f32 "
                 "{%0,%1,%2,%3}, {%4,%5,%6,%7}, {%8,%9}, {%0,%1,%2,%3};"
                 : "+f"(c[0]), "+f"(c[1]), "+f"(c[2]), "+f"(c[3])
                 : "r"(a0), "r"(a1), "r"(a2), "r"(a3), "r"(b0), "r"(b1));
}
__device__ __forceinline__ int mask1(const void* p, long long i, int code) {
    if (code == 0) return ((const unsigned char*)p)[i] != 0;
    if (code == 1) return ((const int*)p)[i] != 0;
    return ((const float*)p)[i] != 0.0f;
}
__device__ __forceinline__ int4 mask4(const void* p, int i4, int code) {
    if (code == 0) {
        uchar4 m = ((const uchar4*)p)[i4];
        return make_int4(m.x != 0, m.y != 0, m.z != 0, m.w != 0);
    }
    if (code == 1) {
        int4 m = ((const int4*)p)[i4];
        return make_int4(m.x != 0, m.y != 0, m.z != 0, m.w != 0);
    }
    float4 m = ((const float4*)p)[i4];
    return make_int4(m.x != 0.0f, m.y != 0.0f, m.z != 0.0f, m.w != 0.0f);
}
__device__ __forceinline__ uint32_t swz(uint32_t o) { return o ^ ((o >> 3) & 0x70); }
__device__ __forceinline__ uint32_t abA(int row, int col) {   // 128-row bf16 tile
    uint32_t o = (uint32_t)((row >> 3) + (col >> 6) * 16) * 1024u
               + (uint32_t)(row & 7) * 128u + (uint32_t)(col & 63) * 2u;
    return swz(o);
}
__device__ __forceinline__ uint32_t abW2(int row, int col) {  // 32-row bf16 tile
    uint32_t o = (uint32_t)((row >> 3) + (col >> 6) * 4) * 1024u
               + (uint32_t)(row & 7) * 128u + (uint32_t)(col & 63) * 2u;
    return swz(o);
}

// ---------------- SMEM layout ----------------
#define SM_BATCH   0               // 128*4
#define SM_B1      512             // 128*4
#define SM_B2      1024            // 32*4
#define SM_A       2048            // 128x128 bf16 = 32768
#define SM_W1      34816           // 128x128 bf16 = 32768
#define SM_W2      67584           // 32x128 bf16  = 8192
#define SM_GB      75776           // 64x128 f32   = 32768
#define SMEM_TOTAL 108544

// ---------------- grid barrier (all CTAs resident) ----------------
__device__ __forceinline__ void grid_barrier(unsigned sense) {
    __syncthreads();
    if (threadIdx.x == 0) {
        __threadfence();
        unsigned arrived = atomicAdd(&d_barcnt, 1u);
        if (arrived == gridDim.x - 1) {
            d_barcnt = 0;
            __threadfence();
            d_barsense = sense;
        } else {
            while (d_barsense != sense) { __nanosleep(64); }
        }
        __threadfence();
    }
    __syncthreads();
}

// ---------------- the whole problem in one persistent kernel ----------------
__global__ void __launch_bounds__(256, 2)
cube_all_kernel(const float* __restrict__ nf, const float* __restrict__ gf,
                const float* __restrict__ W1, const float* __restrict__ b1,
                const float* __restrict__ W2, const float* __restrict__ b2,
                const void* __restrict__ cmask, const int* __restrict__ batch,
                const void* __restrict__ mmask, float* __restrict__ out)
{
    extern __shared__ char smem[];
    __shared__ int s_red[256];      // scan scratch
    uint32_t sb = smem_u32(smem);
    int tid = threadIdx.x, wid = tid >> 5, lid = tid & 31;

    // ================= P0: NEG prefill + dtype detect =================
    {
        float4 v = make_float4(NEGV, NEGV, NEGV, NEGV);
        for (int i = blockIdx.x * 256 + tid; i < OUT_ELEMS / 4; i += gridDim.x * 256)
            ((float4*)out)[i] = v;
        if (blockIdx.x == 0 && tid == 0) {
            for (int which = 0; which < 2; which++) {
                const uint32_t* p = which ? (const uint32_t*)mmask : (const uint32_t*)cmask;
                int isf32 = 0, isu8 = 0;
                for (int i = 0; i < 256; i++) {
                    uint32_t v2 = p[i];
                    if (v2 == 0x3F800000u) { isf32 = 1; break; }
                    if (v2 > 1u) isu8 = 1;
                }
                d_mcode[which] = isf32 ? 2 : (isu8 ? 0 : 1);
            }
        }
    }
    grid_barrier(1);
    const int ccode = d_mcode[0];
    const int mcode = d_mcode[1];

    // ================= P1: per-1024-node partial sums =================
    for (int vb = blockIdx.x; vb < 256; vb += gridDim.x) {
        int4 m = mask4(cmask, vb * 256 + tid, ccode);
        int s = m.x + m.y + m.z + m.w;
        for (int o = 16; o; o >>= 1) s += __shfl_down_sync(0xFFFFFFFFu, s, o);
        if (lid == 0) s_red[wid] = s;
        __syncthreads();
        if (tid == 0) {
            int tot = 0;
            #pragma unroll
            for (int i = 0; i < 8; i++) tot += s_red[i];
            d_blocksum[vb] = tot;
        }
        __syncthreads();
    }
    grid_barrier(2);

    // ================= P2: block-offset prefix (CTA 0) =================
    if (blockIdx.x == 0) {
        int own = d_blocksum[tid];
        s_red[tid] = own;
        __syncthreads();
        for (int o = 1; o < 256; o <<= 1) {
            int v = (tid >= o) ? s_red[tid - o] : 0;
            __syncthreads();
            s_red[tid] += v;
            __syncthreads();
        }
        d_blockoff[tid] = s_red[tid] - own;
    }
    grid_barrier(3);

    // ================= P3: final exclusive scan + graph starts =================
    for (int vb = blockIdx.x; vb < 256; vb += gridDim.x) {
        int n0 = vb * 1024 + tid * 4;
        int4 m = mask4(cmask, n0 >> 2, ccode);
        int c0 = m.x, c1 = m.y, c2 = m.z, c3 = m.w;
        int s = c0 + c1 + c2 + c3;
        int incl = s;
        for (int o = 1; o < 32; o <<= 1) {
            int v = __shfl_up_sync(0xFFFFFFFFu, incl, o);
            if (lid >= o) incl += v;
        }
        if (lid == 31) s_red[wid] = incl;
        __syncthreads();
        int wbase = 0;
        for (int i = 0; i < wid; i++) wbase += s_red[i];
        int e0 = d_blockoff[vb] + wbase + incl - s;
        int e1 = e0 + c0, e2 = e1 + c1, e3 = e2 + c2;
        d_excl[n0 + 0] = e0; d_excl[n0 + 1] = e1;
        d_excl[n0 + 2] = e2; d_excl[n0 + 3] = e3;
        int bp = (n0 == 0) ? -1 : batch[n0 - 1];
        int b0 = batch[n0 + 0], b1v = batch[n0 + 1], b2v = batch[n0 + 2], b3v = batch[n0 + 3];
        if (b0 != bp)   d_gstart[b0]  = e0;
        if (b1v != b0)  d_gstart[b1v] = e1;
        if (b2v != b1v) d_gstart[b2v] = e2;
        if (b3v != b2v) d_gstart[b3v] = e3;
        __syncthreads();
    }
    grid_barrier(4);

    // ================= per-CTA one-time staging =================
    // biases
    if (tid < 128) ((float*)(smem + SM_B1))[tid] = b1[tid];
    if (tid < 32)  ((float*)(smem + SM_B2))[tid] = (tid < NM) ? b2[tid] : 0.0f;
    // G (bf16, swizzled) -> A region rows 0..63 ; W1b (cols 128..255) -> W1 region
    for (int e2 = tid; e2 < 64 * 64; e2 += 256) {
        int row = e2 >> 6, col = (e2 & 63) * 2;
        float2 v = *(const float2*)(gf + row * 128 + col);
        *(uint32_t*)(smem + SM_A + abA(row, col)) = packbf(v.x, v.y);
    }
    for (int e2 = tid; e2 < 128 * 64; e2 += 256) {
        int row = e2 >> 6, col = (e2 & 63) * 2;
        float2 v = *(const float2*)(W1 + row * 256 + 128 + col);
        *(uint32_t*)(smem + SM_W1 + abA(row, col)) = packbf(v.x, v.y);
    }
    // W2 pad + stage
    for (int i = tid; i < 8192 / 4; i += 256) ((uint32_t*)(smem + SM_W2))[i] = 0;
    __syncthreads();
    for (int e2 = tid; e2 < 24 * 64; e2 += 256) {
        int row = e2 >> 6, col = (e2 & 63) * 2;
        float2 v = *(const float2*)(W2 + row * 128 + col);
        *(uint32_t*)(smem + SM_W2 + abW2(row, col)) = packbf(v.x, v.y);
    }
    __syncthreads();

    const float* b1s = (const float*)(smem + SM_B1);
    const float* b2s = (const float*)(smem + SM_B2);
    int* sbatch = (int*)(smem + SM_BATCH);
    float* GBp = (float*)(smem + SM_GB);

    const int m0 = wid * 16;
    const int mrow = lid >> 2;
    const int kcol2 = (lid & 3) * 2;
    const int lm_row = lid & 15;
    const int lm_kof = (lid >> 4) << 3;
    const int brow0 = (lid & 7) + ((lid >> 4) << 3);

    // ---- GB[64][128] = G @ W1b^T + b1 (warps 0..3, tensor cores) ----
    if (wid < 4) {
        float acc[16][4];
        #pragma unroll
        for (int nb = 0; nb < 16; nb++)
            acc[nb][0] = acc[nb][1] = acc[nb][2] = acc[nb][3] = 0.0f;
        #pragma unroll
        for (int kk = 0; kk < 8; kk++) {
            int k0 = kk * 16;
            uint32_t a0, a1, a2, a3;
            ldsm4(a0, a1, a2, a3, sb + SM_A + abA(m0 + lm_row, k0 + lm_kof));
            #pragma unroll
            for (int nbp = 0; nbp < 8; nbp++) {
                uint32_t b0, b1r, b2r, b3;
                ldsm4(b0, b1r, b2r, b3, sb + SM_W1 + abA(nbp * 16 + brow0, k0 + (lid & 8)));
                mma16816(acc[2 * nbp],     a0, a1, a2, a3, b0, b1r);
                mma16816(acc[2 * nbp + 1], a0, a1, a2, a3, b2r, b3);
            }
        }
        #pragma unroll
        for (int nb = 0; nb < 16; nb++) {
            int col = nb * 8 + kcol2;
            float2 lo = make_float2(acc[nb][0] + b1s[col], acc[nb][1] + b1s[col + 1]);
            float2 hi = make_float2(acc[nb][2] + b1s[col], acc[nb][3] + b1s[col + 1]);
            *(float2*)&GBp[(m0 + mrow) * 128 + col]     = lo;
            *(float2*)&GBp[(m0 + mrow + 8) * 128 + col] = hi;
        }
    }
    __syncthreads();
    // ---- now stage W1a (cols 0..127) over W1 region ----
    for (int e2 = tid; e2 < 128 * 64; e2 += 256) {
        int row = e2 >> 6, col = (e2 & 63) * 2;
        float2 v = *(const float2*)(W1 + row * 256 + col);
        *(uint32_t*)(smem + SM_W1 + abA(row, col)) = packbf(v.x, v.y);
    }
    __syncthreads();

    // ================= tile loop =================
    for (int tile = blockIdx.x; tile < NTILES; tile += gridDim.x) {
        int nbase = tile * TILE_M;
        if (tid < 128) sbatch[tid] = batch[nbase + tid];
        // stage A node tile: 128x128 f32 -> bf16 swizzled
        #pragma unroll
        for (int it = 0; it < 16; it++) {
            int i4 = tid + it * 256;
            int row = i4 >> 5, col = (i4 & 31) * 4;
            float4 v = *(const float4*)(nf + (size_t)(nbase + row) * ND + col);
            uint2 pp = make_uint2(packbf(v.x, v.y), packbf(v.z, v.w));
            *(uint2*)(smem + SM_A + abA(row, col)) = pp;
        }
        __syncthreads();

        // ---- GEMM1: D[128,128] = A[128,128] @ W1a^T ----
        float acc[16][4];
        #pragma unroll
        for (int nb = 0; nb < 16; nb++)
            acc[nb][0] = acc[nb][1] = acc[nb][2] = acc[nb][3] = 0.0f;
        #pragma unroll
        for (int kk = 0; kk < 8; kk++) {
            int k0 = kk * 16;
            uint32_t a0, a1, a2, a3;
            ldsm4(a0, a1, a2, a3, sb + SM_A + abA(m0 + lm_row, k0 + lm_kof));
            #pragma unroll
            for (int nbp = 0; nbp < 8; nbp++) {
                uint32_t b0, b1r, b2r, b3;
                ldsm4(b0, b1r, b2r, b3, sb + SM_W1 + abA(nbp * 16 + brow0, k0 + (lid & 8)));
                mma16816(acc[2 * nbp],     a0, a1, a2, a3, b0, b1r);
                mma16816(acc[2 * nbp + 1], a0, a1, a2, a3, b2r, b3);
            }
        }

        // ---- GEMM2 (register-chained): S[128,24] = relu(D+GB[bg]) @ W2^T ----
        const int bgA = sbatch[m0 + mrow];
        const int bgB = sbatch[m0 + mrow + 8];
        const float* gbA = &GBp[bgA * 128];
        const float* gbB = &GBp[bgB * 128];
        float acc2[3][4];
        #pragma unroll
        for (int nb = 0; nb < 3; nb++)
            acc2[nb][0] = acc2[nb][1] = acc2[nb][2] = acc2[nb][3] = 0.0f;
        #pragma unroll
        for (int kk2 = 0; kk2 < 8; kk2++) {
            int col0 = kk2 * 16 + kcol2;
            int col1 = col0 + 8;
            float2 rA0 = *(const float2*)&gbA[col0];
            float2 rB0 = *(const float2*)&gbB[col0];
            float2 rA1 = *(const float2*)&gbA[col1];
            float2 rB1 = *(const float2*)&gbB[col1];
            uint32_t a0 = packbf(fmaxf(acc[2 * kk2][0] + rA0.x, 0.0f),
                                 fmaxf(acc[2 * kk2][1] + rA0.y, 0.0f));
            uint32_t a1 = packbf(fmaxf(acc[2 * kk2][2] + rB0.x, 0.0f),
                                 fmaxf(acc[2 * kk2][3] + rB0.y, 0.0f));
            uint32_t a2 = packbf(fmaxf(acc[2 * kk2 + 1][0] + rA1.x, 0.0f),
                                 fmaxf(acc[2 * kk2 + 1][1] + rA1.y, 0.0f));
            uint32_t a3 = packbf(fmaxf(acc[2 * kk2 + 1][2] + rB1.x, 0.0f),
                                 fmaxf(acc[2 * kk2 + 1][3] + rB1.y, 0.0f));
            int bcol = kk2 * 16 + (lid & 8);
            uint32_t b0, b1r, b2r, b3;
            ldsm4(b0, b1r, b2r, b3, sb + SM_W2 + abW2(brow0, bcol));
            mma16816(acc2[0], a0, a1, a2, a3, b0, b1r);
            mma16816(acc2[1], a0, a1, a2, a3, b2r, b3);
            ldsm4(b0, b1r, b2r, b3, sb + SM_W2 + abW2(16 + brow0, bcol));
            mma16816(acc2[2], a0, a1, a2, a3, b0, b1r);
        }

        // ---- scatter from registers ----
        #pragma unroll
        for (int rr = 0; rr < 2; rr++) {
            int row = m0 + mrow + rr * 8;
            int node = nbase + row;
            if (mask1(cmask, node, ccode)) {
                int bg = rr ? bgB : bgA;
                int rk = d_excl[node] - d_gstart[bg];
                if (rk < MAXC) {
                    size_t base = ((size_t)bg * MAXC + (size_t)rk) * NM;
                    #pragma unroll
                    for (int nb = 0; nb < 3; nb++) {
                        int c = nb * 8 + kcol2;
                        float v0 = acc2[nb][rr * 2]     + b2s[c];
                        float v1 = acc2[nb][rr * 2 + 1] + b2s[c + 1];
                        if (mask1(mmask, (long long)(base + c), mcode))     out[base + c]     = v0;
                        if (mask1(mmask, (long long)(base + c + 1), mcode)) out[base + c + 1] = v1;
                    }
                }
            }
        }
        __syncthreads();
    }
}

// ---------------- launch ----------------
extern "C" void kernel_launch(void* const* d_in, const int* in_sizes, int n_in,
                              void* d_out, int out_size) {
    const float* nf    = (const float*)d_in[0];
    const float* gf    = (const float*)d_in[1];
    const float* W1    = (const float*)d_in[2];
    const float* b1    = (const float*)d_in[3];
    const float* W2    = (const float*)d_in[4];
    const float* b2    = (const float*)d_in[5];
    const void*  cm    = d_in[6];
    const int*   batch = (const int*)d_in[7];
    const void*  mm    = d_in[8];
    float*       out   = (float*)d_out;

    int sm = 0;
    cudaDeviceGetAttribute(&sm, cudaDevAttrMultiProcessorCount, 0);
    if (sm <= 0) sm = 148;
    cudaFuncSetAttribute(cube_all_kernel, cudaFuncAttributeMaxDynamicSharedMemorySize, SMEM_TOTAL);
    cube_all_kernel<<<sm * 2, 256, SMEM_TOTAL>>>(nf, gf, W1, b1, W2, b2, cm, batch, mm, out);
}